// round 3
// baseline (speedup 1.0000x reference)
#include <cuda_runtime.h>
#include <math.h>

// Problem constants
#define BQ   4096     // both sides fused: [0,2048)=left, [2048,4096)=right
#define BH   2048
#define LVS  64
#define IND  300
#define M    150
#define M3   450
#define HIDD 50
#define NCC  5
#define VMAX 50000

#define TRT  16       // rows per block (tree)
#define VRT  32       // rows per block (vocab GEMM)

// Scratch (uninitialized __device__ globals: no runtime allocation)
__device__ float g_table[VMAX * M3];            // 90 MB: iou(token) with biases folded
__device__ float g_hA[BQ * LVS * M];
__device__ float g_cA[BQ * LVS * M];
__device__ float g_hB[BQ * (LVS / 2) * M];
__device__ float g_cB[BQ * (LVS / 2) * M];
__device__ float g_WdupT[M * 1500];             // tree weights: [k][750 fused cols x2 dup]
__device__ float g_WdupX[IND * 900];            // leaf weights: [k][450 cols x2 dup]

__device__ __forceinline__ float sigf(float x)  { return 1.0f / (1.0f + __expf(-x)); }
__device__ __forceinline__ float tanhf_(float x){ return 1.0f - 2.0f / (__expf(2.0f * x) + 1.0f); }

// ---- packed f32x2 helpers (sm_100+) --------------------------------------
__device__ __forceinline__ void ffma2(unsigned long long& acc,
                                      unsigned long long a,
                                      unsigned long long b) {
    asm("fma.rn.f32x2 %0, %1, %2, %0;" : "+l"(acc) : "l"(a), "l"(b));
}
__device__ __forceinline__ float2 unpack2(unsigned long long v) {
    float2 f;
    asm("mov.b64 {%0, %1}, %2;" : "=f"(f.x), "=f"(f.y) : "l"(v));
    return f;
}

// ---------------------------------------------------------------------------
// Prep: build duplicated, fused weight tables.
//   g_WdupT[k][2c..2c+1] = (c<450) ? Wiouh[k][c] : Wfh[k][(c-450)%150]
//   g_WdupX[k][2c..2c+1] = Wioux[k][c]
// ---------------------------------------------------------------------------
__global__ void __launch_bounds__(256) prep_kernel(
    const float* __restrict__ Wiouh, const float* __restrict__ Wfh,
    const float* __restrict__ Wioux)
{
    int idx = blockIdx.x * 256 + threadIdx.x;
    const int NT = M * 750;          // 112500
    const int NX = IND * M3;         // 135000
    if (idx < NT) {
        int k = idx / 750, c = idx - k * 750;
        float w = (c < M3) ? Wiouh[k * M3 + c]
                           : Wfh[k * M + (c >= 600 ? c - 600 : c - 450)];
        g_WdupT[k * 1500 + 2 * c]     = w;
        g_WdupT[k * 1500 + 2 * c + 1] = w;
    } else if (idx < NT + NX) {
        int j = idx - NT;
        int k = j / M3, c = j - k * M3;
        float w = Wioux[k * M3 + c];
        g_WdupX[k * 900 + 2 * c]     = w;
        g_WdupX[k * 900 + 2 * c + 1] = w;
    }
}

// ---------------------------------------------------------------------------
// Vocab GEMM: table[v] = emb[v] @ Wioux + (bioux + biouh), v in [0, V).
// 256 threads, 32 rows/block. Thread t owns cols {t, t+256}.
// Weights read pre-duplicated (LDG.64, no packing).
// ---------------------------------------------------------------------------
__global__ void __launch_bounds__(256) vocab_kernel(
    const float* __restrict__ emb,
    const float* __restrict__ bx, const float* __restrict__ bhh,
    float* __restrict__ table, int V)
{
    __shared__ __align__(16) float xs[IND * 36];   // 43200 B

    const int t = threadIdx.x;
    const int base = blockIdx.x * VRT;

    for (int idx = t; idx < VRT * IND; idx += 256) {
        int rr = idx / IND, k = idx - rr * IND;
        int row = base + rr;
        if (row >= V) row = V - 1;
        xs[k * 36 + rr] = emb[row * IND + k];
    }
    __syncthreads();

    unsigned long long a0[16], a1[16];
#pragma unroll
    for (int i = 0; i < 16; i++) { a0[i] = 0ull; a1[i] = 0ull; }

    const bool has1 = (t + 256) < M3;   // t < 194
    const float* __restrict__ wbase0 = g_WdupX + 2 * t;
    const float* __restrict__ wbase1 = g_WdupX + (has1 ? 2 * (t + 256) : 0);

#pragma unroll 2
    for (int k = 0; k < IND; k++) {
        unsigned long long pw0 = *reinterpret_cast<const unsigned long long*>(wbase0 + k * 900);
        unsigned long long pw1 = *reinterpret_cast<const unsigned long long*>(wbase1 + k * 900);
        const ulonglong2* xp = reinterpret_cast<const ulonglong2*>(xs + k * 36);
#pragma unroll
        for (int p = 0; p < 8; p++) {
            ulonglong2 v = xp[p];                 // rows 4p..4p+3
            ffma2(a0[2 * p],     v.x, pw0);
            ffma2(a0[2 * p + 1], v.y, pw0);
            ffma2(a1[2 * p],     v.x, pw1);
            ffma2(a1[2 * p + 1], v.y, pw1);
        }
    }

    float b0 = bx[t] + bhh[t];
    float b1 = has1 ? (bx[t + 256] + bhh[t + 256]) : 0.f;
#pragma unroll
    for (int pr = 0; pr < 16; pr++) {
        int r0 = base + 2 * pr, r1 = r0 + 1;
        float2 v0 = unpack2(a0[pr]);
        if (r0 < V) table[r0 * M3 + t] = v0.x + b0;
        if (r1 < V) table[r1 * M3 + t] = v0.y + b0;
        if (has1) {
            float2 v1 = unpack2(a1[pr]);
            if (r0 < V) table[r0 * M3 + t + 256] = v1.x + b1;
            if (r1 < V) table[r1 * M3 + t + 256] = v1.y + b1;
        }
    }
}

// ---------------------------------------------------------------------------
// Leaf lookup: per element (row, j): read table[tok][{j, j+M, j+2M}], gates.
// ---------------------------------------------------------------------------
__global__ void __launch_bounds__(256) leaf_lookup_kernel(
    const int* __restrict__ ltok, const int* __restrict__ rtok,
    const float* __restrict__ table,
    float* __restrict__ h_out, float* __restrict__ c_out)
{
    int idx = blockIdx.x * 256 + threadIdx.x;     // < BQ*LVS*M
    int row = idx / M;
    int j = idx - row * M;
    int q = row >> 6, l = row & 63;
    int tok = (q < BH) ? ltok[q * LVS + l] : rtok[(q - BH) * LVS + l];
    const float* tr = table + tok * M3;
    float iv = sigf(tr[j]);
    float ov = sigf(tr[j + M]);
    float uv = tanhf_(tr[j + 2 * M]);
    float cv = iv * uv;
    float hv = ov * tanhf_(cv);
    c_out[idx] = cv;
    h_out[idx] = hv;
}

// ---------------------------------------------------------------------------
// Tree level kernel. Output row r reads children 2r, 2r+1.
// Fused 750-wide result: [0,450)=iou(hs), [450,600)=f0(h0), [600,750)=f1(h1).
// 256 threads, thread t owns slots 3t..3t+2 (region-uniform per thread).
// Weights from g_WdupT (fused cols, duplicated): 3x LDG.64 per k, no packs,
// no per-region weight addressing.
// ---------------------------------------------------------------------------
__global__ void __launch_bounds__(256) tree_kernel(
    const float* __restrict__ h_in, const float* __restrict__ c_in,
    float* __restrict__ h_out, float* __restrict__ c_out,
    const float* __restrict__ biouh, const float* __restrict__ bfh)
{
    __shared__ __align__(16) float sm[12096];   // 48384 B; tiles use first 9000 floats
    const int t = threadIdx.x;
    const int base = blockIdx.x * TRT;

    float* HS = sm;            // [k*20 + rr]
    float* H0 = sm + 3000;
    float* H1 = sm + 6000;

    for (int idx = t; idx < TRT * M; idx += 256) {
        int rr = idx / M, k = idx - rr * M;
        int orow = base + rr;
        float a = h_in[(2 * orow) * M + k];
        float b = h_in[(2 * orow + 1) * M + k];
        HS[k * 20 + rr] = a + b;
        H0[k * 20 + rr] = a;
        H1[k * 20 + rr] = b;
    }
    __syncthreads();

    const int slot0 = 3 * t;
    const bool active = slot0 < 750;
    const int region = (slot0 < 450) ? 0 : ((slot0 < 600) ? 1 : 2);

    const float* tile = (region == 0) ? HS : ((region == 1) ? H0 : H1);
    const float* __restrict__ wb = g_WdupT + (active ? 2 * slot0 : 0);

    unsigned long long a0[8], a1[8], a2[8];
#pragma unroll
    for (int i = 0; i < 8; i++) { a0[i] = 0ull; a1[i] = 0ull; a2[i] = 0ull; }

#pragma unroll 4
    for (int k = 0; k < M; k++) {
        const float* wk = wb + k * 1500;
        unsigned long long pw0 = *reinterpret_cast<const unsigned long long*>(wk);
        unsigned long long pw1 = *reinterpret_cast<const unsigned long long*>(wk + 2);
        unsigned long long pw2 = *reinterpret_cast<const unsigned long long*>(wk + 4);
        const ulonglong2* tp = reinterpret_cast<const ulonglong2*>(tile + k * 20);
#pragma unroll
        for (int p = 0; p < 4; p++) {
            ulonglong2 v = tp[p];                 // rows 4p..4p+3 (broadcast)
            ffma2(a0[2 * p],     v.x, pw0);
            ffma2(a0[2 * p + 1], v.y, pw0);
            ffma2(a1[2 * p],     v.x, pw1);
            ffma2(a1[2 * p + 1], v.y, pw1);
            ffma2(a2[2 * p],     v.x, pw2);
            ffma2(a2[2 * p + 1], v.y, pw2);
        }
    }
    __syncthreads();   // tiles fully consumed; reuse sm as res[rr][756]

    if (active) {
        float bb0, bb1, bb2;
        if (region == 0)      { bb0 = biouh[slot0];     bb1 = biouh[slot0 + 1];     bb2 = biouh[slot0 + 2];     }
        else if (region == 1) { bb0 = bfh[slot0 - 450]; bb1 = bfh[slot0 - 449];     bb2 = bfh[slot0 - 448];     }
        else                  { bb0 = bfh[slot0 - 600]; bb1 = bfh[slot0 - 599];     bb2 = bfh[slot0 - 598];     }
#pragma unroll
        for (int p = 0; p < 8; p++) {
            float2 v0 = unpack2(a0[p]);
            float2 v1 = unpack2(a1[p]);
            float2 v2 = unpack2(a2[p]);
            float* r0 = sm + (2 * p) * 756;
            float* r1 = sm + (2 * p + 1) * 756;
            r0[slot0]     = v0.x + bb0;  r1[slot0]     = v0.y + bb0;
            r0[slot0 + 1] = v1.x + bb1;  r1[slot0 + 1] = v1.y + bb1;
            r0[slot0 + 2] = v2.x + bb2;  r1[slot0 + 2] = v2.y + bb2;
        }
    }
    __syncthreads();

    for (int idx = t; idx < TRT * M; idx += 256) {
        int rr = idx / M, j = idx - rr * M;
        const float* r = sm + rr * 756;
        float iv = sigf(r[j]);
        float ov = sigf(r[j + 150]);
        float uv = tanhf_(r[j + 300]);
        float f0 = sigf(r[450 + j]);
        float f1 = sigf(r[600 + j]);
        int orow = base + rr;
        float c0 = c_in[(2 * orow) * M + j];
        float c1 = c_in[(2 * orow + 1) * M + j];
        float cv = iv * uv + f0 * c0 + f1 * c1;
        float hv = ov * tanhf_(cv);
        c_out[orow * M + j] = cv;
        h_out[orow * M + j] = hv;
    }
}

// ---------------------------------------------------------------------------
// Classifier: vec = [lh*rh, |lh-rh|]; mid = sig(vec@Wh + bh);
// out = log_softmax(mid@Wp + bp). One block (64 thr) per pair.
// ---------------------------------------------------------------------------
__global__ void __launch_bounds__(64) cls_kernel(
    const float* __restrict__ hfin,
    const float* __restrict__ Wh, const float* __restrict__ bh,
    const float* __restrict__ Wp, const float* __restrict__ bp,
    float* __restrict__ out)
{
    __shared__ float vec[2 * M];
    __shared__ float mid[HIDD];
    __shared__ float logits[NCC];

    const int q = blockIdx.x;
    const int t = threadIdx.x;
    const float* lh = hfin + q * M;
    const float* rh = hfin + (BH + q) * M;

    for (int j = t; j < M; j += 64) {
        float a = lh[j], b = rh[j];
        vec[j]     = a * b;
        vec[M + j] = fabsf(a - b);
    }
    __syncthreads();

    if (t < HIDD) {
        float s = bh[t];
        for (int j = 0; j < 2 * M; j++) s += vec[j] * Wh[j * HIDD + t];
        mid[t] = sigf(s);
    }
    __syncthreads();

    if (t < NCC) {
        float s = bp[t];
        for (int h = 0; h < HIDD; h++) s += mid[h] * Wp[h * NCC + t];
        logits[t] = s;
    }
    __syncthreads();

    if (t == 0) {
        float mx = logits[0];
        for (int c = 1; c < NCC; c++) mx = fmaxf(mx, logits[c]);
        float sum = 0.f;
        for (int c = 0; c < NCC; c++) sum += expf(logits[c] - mx);
        float lse = mx + logf(sum);
        for (int c = 0; c < NCC; c++) out[q * NCC + c] = logits[c] - lse;
    }
}

// ---------------------------------------------------------------------------
extern "C" void kernel_launch(void* const* d_in, const int* in_sizes, int n_in,
                              void* d_out, int out_size)
{
    (void)n_in; (void)out_size;
    const int*   ltok  = (const int*)d_in[0];
    const int*   rtok  = (const int*)d_in[1];
    const float* emb   = (const float*)d_in[2];
    const float* Wioux = (const float*)d_in[3];
    const float* bioux = (const float*)d_in[4];
    const float* Wiouh = (const float*)d_in[5];
    const float* biouh = (const float*)d_in[6];
    // d_in[7] = Wfx, d_in[8] = bfx : unused by the reference computation
    const float* Wfh   = (const float*)d_in[9];
    const float* bfh   = (const float*)d_in[10];
    const float* Wh    = (const float*)d_in[11];
    const float* bh    = (const float*)d_in[12];
    const float* Wp    = (const float*)d_in[13];
    const float* bp    = (const float*)d_in[14];
    float* out = (float*)d_out;

    int V = in_sizes[2] / IND;
    if (V > VMAX) V = VMAX;

    void* p;
    float *hA, *cA, *hB, *cB, *table;
    cudaGetSymbolAddress(&p, g_table); table = (float*)p;
    cudaGetSymbolAddress(&p, g_hA); hA = (float*)p;
    cudaGetSymbolAddress(&p, g_cA); cA = (float*)p;
    cudaGetSymbolAddress(&p, g_hB); hB = (float*)p;
    cudaGetSymbolAddress(&p, g_cB); cB = (float*)p;

    // 0) Duplicated/fused weight tables
    prep_kernel<<<(M * 750 + IND * M3 + 255) / 256, 256>>>(Wiouh, Wfh, Wioux);

    // 1) Vocab-deduped leaf GEMM: table[v] = emb[v]@Wioux + bioux + biouh
    vocab_kernel<<<(V + VRT - 1) / VRT, 256>>>(emb, bioux, biouh, table, V);

    // 2) Leaves: gate nonlinearities from table lookups
    leaf_lookup_kernel<<<(BQ * LVS * M) / 256, 256>>>(ltok, rtok, table, hA, cA);

    // 3) 6 tree levels, ping-pong A <-> B
    const float* hin = hA; const float* cin = cA;
    float* ho = hB; float* co = cB;
    for (int n_out = LVS / 2; n_out >= 1; n_out >>= 1) {
        tree_kernel<<<(BQ * n_out) / TRT, 256>>>(hin, cin, ho, co, biouh, bfh);
        const float* th = hin; const float* tc = cin;
        hin = ho; cin = co;
        ho = (float*)th; co = (float*)tc;
    }
    // After 6 swaps, final state (4096 rows x 150) is back in g_hA

    // 4) Classifier
    cls_kernel<<<BH, 64>>>(hin, Wh, bh, Wp, bp, out);
}